// round 6
// baseline (speedup 1.0000x reference)
#include <cuda_runtime.h>
#include <cstdint>

#define FIN   256
#define FOUT  256
#define BATCH 65536
#define BM    64                           // batch rows per tile
#define NTILES (BATCH / BM)                // 1024
#define GRID_B 296                         // 2 CTAs per SM on 148 SMs
#define WSTRIDE 272                        // padded smem row stride (bytes)
#define CSTRIDE 256                        // codes row stride
#define SM_W 0
#define SM_X (FOUT * WSTRIDE)              // 69632
#define SM_C (SM_X + BM * WSTRIDE)         // 87040
#define SMEM_B (SM_C + BM * CSTRIDE)       // 103424 bytes

// ---------------- device scratch ----------------
__device__ unsigned int g_bmax[64];             // per-block |w| max bits
__device__ float        g_params[2];            // [0]=scale_w, [1]=scale_w/15
__device__ int          g_csum [FOUT];
__device__ int          g_csum2[FOUT];
__device__ __align__(16) signed char g_wq[FOUT*FIN];   // quantized weights s8
__device__ signed char  g_codes[(size_t)BATCH*FOUT];   // 16MB int8 acc codes
__device__ float        g_tab[FOUT * 33];       // out = f(channel, code)

// ---------------- helpers ----------------
__device__ __forceinline__ void mma_u8s8(int* c, const unsigned* a, unsigned b0, unsigned b1) {
    asm volatile(
        "mma.sync.aligned.m16n8k32.row.col.s32.u8.s8.s32 "
        "{%0,%1,%2,%3},{%4,%5,%6,%7},{%8,%9},{%0,%1,%2,%3};"
        : "+r"(c[0]), "+r"(c[1]), "+r"(c[2]), "+r"(c[3])
        : "r"(a[0]), "r"(a[1]), "r"(a[2]), "r"(a[3]), "r"(b0), "r"(b1));
}
__device__ __forceinline__ unsigned qact(float v) {
    return (unsigned)(int)rintf(fminf(fmaxf(v, 0.0f), 1.0f) * 15.0f);
}
// exact round-half-even(p/1792), p integer in [-13440, 13440]
__device__ __forceinline__ int rne1792(int p) {
    unsigned pp = (unsigned)(p + 15232);          // p + 896 + 8*1792 >= 0
    unsigned q = pp / 1792u;                      // umulhi + shift
    unsigned rem = pp - q * 1792u;
    int r = (int)q - 8;
    if (rem == 0u) r -= (r & 1);                  // tie -> even
    return r;
}

// ---------------- kernel A0: zero stat accumulators ----------------
__global__ void kA0() {
    int t = threadIdx.x;
    g_csum[t]  = 0;
    g_csum2[t] = 0;
}

// ---------------- kernel A1: per-block max|W| ----------------
__global__ void kA1(const float* __restrict__ w) {
    int j = blockIdx.x * 256 + threadIdx.x;       // float4 id, 16384 total
    float4 v = ((const float4*)w)[j];
    unsigned m = max(max(__float_as_uint(fabsf(v.x)), __float_as_uint(fabsf(v.y))),
                     max(__float_as_uint(fabsf(v.z)), __float_as_uint(fabsf(v.w))));
    #pragma unroll
    for (int o = 16; o; o >>= 1) m = max(m, __shfl_xor_sync(0xffffffffu, m, o));
    __shared__ unsigned sm[8];
    if ((threadIdx.x & 31) == 0) sm[threadIdx.x >> 5] = m;
    __syncthreads();
    if (threadIdx.x == 0) {
        #pragma unroll
        for (int i = 1; i < 8; i++) m = max(m, sm[i]);
        g_bmax[blockIdx.x] = m;
    }
}

// ---------------- kernel A2: reduce max, quantize weights ----------------
__global__ void kA2(const float* __restrict__ w) {
    __shared__ unsigned sm[64];
    __shared__ float sscale;
    int tid = threadIdx.x;
    if (tid < 64) sm[tid] = g_bmax[tid];
    __syncthreads();
    if (tid == 0) {
        unsigned m = sm[0];
        #pragma unroll
        for (int i = 1; i < 64; i++) m = max(m, sm[i]);
        float scale = __fdiv_rn(__uint_as_float(m), 7.0f);
        sscale = scale;
        if (blockIdx.x == 0) {
            g_params[0] = scale;
            g_params[1] = __fdiv_rn(scale, 15.0f);
        }
    }
    __syncthreads();
    float scale = sscale;
    int j = blockIdx.x * 256 + tid;               // float4 id
    float4 v = ((const float4*)w)[j];
    char4 q;
    q.x = (signed char)(int)rintf(fminf(fmaxf(__fdiv_rn(v.x, scale), -7.0f), 7.0f));
    q.y = (signed char)(int)rintf(fminf(fmaxf(__fdiv_rn(v.y, scale), -7.0f), 7.0f));
    q.z = (signed char)(int)rintf(fminf(fmaxf(__fdiv_rn(v.z, scale), -7.0f), 7.0f));
    q.w = (signed char)(int)rintf(fminf(fmaxf(__fdiv_rn(v.w, scale), -7.0f), 7.0f));
    ((char4*)g_wq)[j] = q;
}

// ---------------- kernel B: pipelined multi-tile IMMA GEMM ----------------
__global__ void __launch_bounds__(256, 2) kB(const float* __restrict__ x) {
    extern __shared__ unsigned char sm[];
    unsigned char* w_s   = sm + SM_W;             // [256][272] s8 weights
    unsigned char* x_s   = sm + SM_X;             // [64][272] u8 activation codes
    signed char*   codes = (signed char*)(sm + SM_C);  // [64][256] output codes

    const int tid = threadIdx.x, warp = tid >> 5, lane = tid & 31;
    const int g = lane >> 2, tq = lane & 3;
    const int m0 = (warp & 3) * 16;               // m16 fragment base row
    const int n0 = (warp >> 2) * 128;             // n-half

    // --- load quantized weights once per CTA ---
    {
        const int4* wg = (const int4*)g_wq;
        #pragma unroll
        for (int i = 0; i < 16; i++) {
            int j = tid + i * 256;                // int4 idx 0..4095
            int row = j >> 4, col = j & 15;
            *(int4*)(w_s + row * WSTRIDE + col * 16) = wg[j];
        }
    }
    // --- load + quantize first tile into x_s ---
    {
        const float4* xg = (const float4*)(x + (size_t)blockIdx.x * BM * FIN);
        #pragma unroll
        for (int i = 0; i < 16; i++) {
            int j = tid + i * 256;                // float4 idx 0..4095
            float4 v = xg[j];
            int row = j >> 6, c4 = j & 63;
            unsigned p = qact(v.x) | (qact(v.y) << 8) | (qact(v.z) << 16) | (qact(v.w) << 24);
            *(unsigned*)(x_s + row * WSTRIDE + c4 * 4) = p;
        }
    }
    __syncthreads();

    int sacc = 0, s2acc = 0;                      // per-channel stats across tiles

    #pragma unroll 1
    for (int tile = blockIdx.x; tile < NTILES; tile += GRID_B) {
        const int next = tile + GRID_B;
        const bool havenext = next < NTILES;
        const float4* xg_next = (const float4*)(x + (size_t)next * BM * FIN);

        // --- preload A fragments for this tile (x_s dead afterwards) ---
        unsigned a[8][4];
        #pragma unroll
        for (int tk = 0; tk < 8; tk++) {
            int koff = tk * 32;
            a[tk][0] = *(const unsigned*)(x_s + (m0 + g    ) * WSTRIDE + koff +      tq * 4);
            a[tk][1] = *(const unsigned*)(x_s + (m0 + g + 8) * WSTRIDE + koff +      tq * 4);
            a[tk][2] = *(const unsigned*)(x_s + (m0 + g    ) * WSTRIDE + koff + 16 + tq * 4);
            a[tk][3] = *(const unsigned*)(x_s + (m0 + g + 8) * WSTRIDE + koff + 16 + tq * 4);
        }
        __syncthreads();                          // x_s free -> prefetch target

        // --- MMA loop with interleaved next-tile prefetch ---
        #pragma unroll 2
        for (int nf = 0; nf < 16; nf++) {
            // prefetch one float4 of next tile, quantize, stage into x_s
            if (havenext) {
                int j = tid + nf * 256;           // float4 idx 0..4095
                float4 v = xg_next[j];
                int row = j >> 6, c4 = j & 63;
                unsigned p = qact(v.x) | (qact(v.y) << 8) | (qact(v.z) << 16) | (qact(v.w) << 24);
                *(unsigned*)(x_s + row * WSTRIDE + c4 * 4) = p;
            }

            const int nrow = n0 + nf * 8 + g;
            int rr[4] = {0, 0, 0, 0};
            #pragma unroll
            for (int t = 0; t < 2; t++) {
                int c[4] = {0, 0, 0, 0};
                #pragma unroll
                for (int k = 0; k < 4; k++) {
                    int koff = t * 128 + k * 32;
                    unsigned b0 = *(const unsigned*)(w_s + nrow * WSTRIDE + koff +      tq * 4);
                    unsigned b1 = *(const unsigned*)(w_s + nrow * WSTRIDE + koff + 16 + tq * 4);
                    mma_u8s8(c, a[t * 4 + k], b0, b1);
                }
                #pragma unroll
                for (int e = 0; e < 4; e++) rr[e] += rne1792(c[e]);
            }
            int col = n0 + nf * 8 + tq * 2;
            unsigned short p01 = (unsigned short)((rr[0] & 0xFF) | ((rr[1] & 0xFF) << 8));
            unsigned short p23 = (unsigned short)((rr[2] & 0xFF) | ((rr[3] & 0xFF) << 8));
            *(unsigned short*)(codes + (m0 + g    ) * CSTRIDE + col) = p01;
            *(unsigned short*)(codes + (m0 + g + 8) * CSTRIDE + col) = p23;
        }
        __syncthreads();

        // --- per-channel integer stats (column tid) ---
        #pragma unroll
        for (int r = 0; r < BM; r++) {
            int v = (int)codes[r * CSTRIDE + tid];
            sacc += v; s2acc += v * v;
        }
        // --- coalesced code writeout ---
        {
            int4* dst = (int4*)(g_codes + (size_t)tile * BM * FOUT);
            const int4* src = (const int4*)codes;
            #pragma unroll
            for (int i = 0; i < 4; i++)
                dst[tid + i * 256] = src[tid + i * 256];
        }
        __syncthreads();                          // codes_s reads done before next MMA
    }

    atomicAdd(&g_csum [tid], sacc);
    atomicAdd(&g_csum2[tid], s2acc);
}

// ---------------- kernel C: finalize BN stats + build output table ----------------
__global__ void kC(const float* __restrict__ gamma, const float* __restrict__ beta) {
    int o = threadIdx.x;
    float sw15 = g_params[1];
    double C  = 1792.0 * (double)sw15;
    double s  = (double)g_csum[o];
    double s2 = (double)g_csum2[o];
    double mu = C * s / 65536.0;
    double m2 = C * C * s2 / 65536.0;
    double var = m2 - mu * mu;
    float t = (float)var + 1e-5f;
    float rs = (float)(1.0 / sqrt((double)t));
    float muf = (float)mu, gm = gamma[o], bt = beta[o];
    #pragma unroll
    for (int n = 0; n < 33; n++) {
        float acc = __fmul_rn((float)((n - 16) * 1792), sw15);
        float y = ((acc - muf) * rs) * gm + bt;
        float q = rintf(fminf(fmaxf(y, 0.0f), 1.0f) * 15.0f);
        g_tab[o * 33 + n] = __fdiv_rn(q, 15.0f);
    }
}

// ---------------- kernel D: pure table gather ----------------
__global__ void __launch_bounds__(256) kD(float* __restrict__ out) {
    __shared__ float tab[FOUT * 33];              // 33792 B
    #pragma unroll
    for (int i = threadIdx.x; i < FOUT * 33; i += 256) tab[i] = g_tab[i];
    __syncthreads();

    size_t base = (size_t)blockIdx.x * 8192 + threadIdx.x;   // char4 indices
    #pragma unroll 4
    for (int i = 0; i < 32; i++) {
        size_t i4 = base + (size_t)i * 256;
        char4 cc = ((const char4*)g_codes)[i4];
        int o = ((int)(i4 & 63)) * 4;
        float4 r;
        r.x = tab[(o + 0) * 33 + (int)cc.x + 16];
        r.y = tab[(o + 1) * 33 + (int)cc.y + 16];
        r.z = tab[(o + 2) * 33 + (int)cc.z + 16];
        r.w = tab[(o + 3) * 33 + (int)cc.w + 16];
        ((float4*)out)[i4] = r;
    }
}

// ---------------- host launch ----------------
extern "C" void kernel_launch(void* const* d_in, const int* in_sizes, int n_in,
                              void* d_out, int out_size) {
    const float* x     = (const float*)d_in[0];
    const float* w     = (const float*)d_in[1];
    const float* gamma = (const float*)d_in[2];
    const float* beta  = (const float*)d_in[3];
    float* out = (float*)d_out;

    cudaFuncSetAttribute(kB, cudaFuncAttributeMaxDynamicSharedMemorySize, SMEM_B);

    kA0<<<1, 256>>>();
    kA1<<<64, 256>>>(w);
    kA2<<<64, 256>>>(w);
    kB <<<GRID_B, 256, SMEM_B>>>(x);
    kC <<<1, 256>>>(gamma, beta);
    kD <<<512, 256>>>(out);                       // 512 * 8192 char4 = 4194304
    (void)in_sizes; (void)n_in; (void)out_size;
}

// round 7
// speedup vs baseline: 1.0320x; 1.0320x over previous
#include <cuda_runtime.h>
#include <cstdint>

#define FIN   256
#define FOUT  256
#define BATCH 65536
#define BM    64          // batch rows per CTA in GEMM pass
#define WSTRIDE 272       // padded smem row stride (bytes) -> conflict-free frag loads
#define SMEM_B (FOUT*WSTRIDE + BM*WSTRIDE)   // 87040 bytes

// ---------------- device scratch ----------------
__device__ unsigned int g_bmax[64];             // per-block |w| max bits
__device__ float        g_params[2];            // [0]=scale_w, [1]=scale_w/15
__device__ int          g_csum [FOUT];
__device__ int          g_csum2[FOUT];
__device__ __align__(16) signed char g_wq[FOUT*FIN];   // quantized weights s8
__device__ signed char  g_codes[(size_t)BATCH*FOUT];   // 16MB int8 acc codes

// ---------------- helpers ----------------
__device__ __forceinline__ void mma_u8s8(int* c, const unsigned* a, unsigned b0, unsigned b1) {
    asm volatile(
        "mma.sync.aligned.m16n8k32.row.col.s32.u8.s8.s32 "
        "{%0,%1,%2,%3},{%4,%5,%6,%7},{%8,%9},{%0,%1,%2,%3};"
        : "+r"(c[0]), "+r"(c[1]), "+r"(c[2]), "+r"(c[3])
        : "r"(a[0]), "r"(a[1]), "r"(a[2]), "r"(a[3]), "r"(b0), "r"(b1));
}
__device__ __forceinline__ unsigned qact(float v) {
    return (unsigned)(int)rintf(fminf(fmaxf(v, 0.0f), 1.0f) * 15.0f);
}
// exact round-half-even(p/1792), p integer in [-13440, 13440]
__device__ __forceinline__ int rne1792(int p) {
    unsigned pp = (unsigned)(p + 15232);          // p + 896 + 8*1792 >= 0
    unsigned q = pp / 1792u;                      // umulhi + shift
    unsigned rem = pp - q * 1792u;
    int r = (int)q - 8;
    if (rem == 0u) r -= (r & 1);                  // tie -> even
    return r;
}

// ---------------- kernel A1: per-block max|W| (+ stat zeroing by block 0) ----------------
__global__ void kA1(const float* __restrict__ w) {
    if (blockIdx.x == 0) {                        // zero accumulators before kB
        g_csum [threadIdx.x] = 0;
        g_csum2[threadIdx.x] = 0;
    }
    int j = blockIdx.x * 256 + threadIdx.x;       // float4 id, 16384 total
    float4 v = ((const float4*)w)[j];
    unsigned m = max(max(__float_as_uint(fabsf(v.x)), __float_as_uint(fabsf(v.y))),
                     max(__float_as_uint(fabsf(v.z)), __float_as_uint(fabsf(v.w))));
    #pragma unroll
    for (int o = 16; o; o >>= 1) m = max(m, __shfl_xor_sync(0xffffffffu, m, o));
    __shared__ unsigned sm[8];
    if ((threadIdx.x & 31) == 0) sm[threadIdx.x >> 5] = m;
    __syncthreads();
    if (threadIdx.x == 0) {
        #pragma unroll
        for (int i = 1; i < 8; i++) m = max(m, sm[i]);
        g_bmax[blockIdx.x] = m;
    }
}

// ---------------- kernel A2: reduce max, quantize weights ----------------
__global__ void kA2(const float* __restrict__ w) {
    __shared__ unsigned sm[64];
    __shared__ float sscale;
    int tid = threadIdx.x;
    if (tid < 64) sm[tid] = g_bmax[tid];
    __syncthreads();
    if (tid == 0) {
        unsigned m = sm[0];
        #pragma unroll
        for (int i = 1; i < 64; i++) m = max(m, sm[i]);
        float scale = __fdiv_rn(__uint_as_float(m), 7.0f);
        sscale = scale;
        if (blockIdx.x == 0) {
            g_params[0] = scale;
            g_params[1] = __fdiv_rn(scale, 15.0f);
        }
    }
    __syncthreads();
    float scale = sscale;
    int j = blockIdx.x * 256 + tid;               // float4 id
    float4 v = ((const float4*)w)[j];
    char4 q;
    q.x = (signed char)(int)rintf(fminf(fmaxf(__fdiv_rn(v.x, scale), -7.0f), 7.0f));
    q.y = (signed char)(int)rintf(fminf(fmaxf(__fdiv_rn(v.y, scale), -7.0f), 7.0f));
    q.z = (signed char)(int)rintf(fminf(fmaxf(__fdiv_rn(v.z, scale), -7.0f), 7.0f));
    q.w = (signed char)(int)rintf(fminf(fmaxf(__fdiv_rn(v.w, scale), -7.0f), 7.0f));
    ((char4*)g_wq)[j] = q;
}

// ---------------- kernel B: quantize x + int8 GEMM + psum-quant + stats ----------------
__global__ void __launch_bounds__(256, 2) kB(const float* __restrict__ x) {
    extern __shared__ unsigned char sm[];
    unsigned char* w_s = sm;                  // [FOUT][WSTRIDE]
    unsigned char* x_s = sm + FOUT * WSTRIDE; // [BM][WSTRIDE], later reused as codes
    signed char*   codes = (signed char*)x_s; // [BM][256]

    const int tid = threadIdx.x;

    // --- load quantized weights (64KB, L2-hot) ---
    const int4* wg = (const int4*)g_wq;
    #pragma unroll
    for (int i = 0; i < 16; i++) {
        int j = tid + i * 256;          // int4 idx 0..4095
        int row = j >> 4, col = j & 15;
        *(int4*)(w_s + row * WSTRIDE + col * 16) = wg[j];
    }
    // --- load + quantize activations ---
    const float4* xg = (const float4*)(x + (size_t)blockIdx.x * BM * FIN);
    #pragma unroll
    for (int i = 0; i < 16; i++) {
        int j = tid + i * 256;          // float4 idx 0..4095
        float4 v = xg[j];
        int row = j >> 6, c4 = j & 63;
        unsigned p = qact(v.x) | (qact(v.y) << 8) | (qact(v.z) << 16) | (qact(v.w) << 24);
        *(unsigned*)(x_s + row * WSTRIDE + c4 * 4) = p;
    }
    __syncthreads();

    const int warp = tid >> 5, lane = tid & 31;
    const int g = lane >> 2, tq = lane & 3;
    const int m0 = (warp & 3) * 16;     // m16 fragment base row
    const int n0 = (warp >> 2) * 128;   // 128 output channels per warp-half

    // --- preload all A fragments for this warp (2 tiles x 4 ksteps) ---
    unsigned a[8][4];
    #pragma unroll
    for (int tk = 0; tk < 8; tk++) {
        int koff = tk * 32;
        a[tk][0] = *(const unsigned*)(x_s + (m0 + g    ) * WSTRIDE + koff +      tq * 4);
        a[tk][1] = *(const unsigned*)(x_s + (m0 + g + 8) * WSTRIDE + koff +      tq * 4);
        a[tk][2] = *(const unsigned*)(x_s + (m0 + g    ) * WSTRIDE + koff + 16 + tq * 4);
        a[tk][3] = *(const unsigned*)(x_s + (m0 + g + 8) * WSTRIDE + koff + 16 + tq * 4);
    }
    __syncthreads();   // x_s region now free -> code staging

    // --- main MMA loop: 16 n-fragments; two crossbar-tile chains interleaved ---
    #pragma unroll 2
    for (int nf = 0; nf < 16; nf++) {
        const int nrow = n0 + nf * 8 + g;        // output channel row in w_s
        const unsigned char* wrow = w_s + nrow * WSTRIDE;
        int c0[4] = {0, 0, 0, 0};                // crossbar tile 0 chain
        int c1[4] = {0, 0, 0, 0};                // crossbar tile 1 chain
        #pragma unroll
        for (int k = 0; k < 4; k++) {
            int k0 = k * 32, k1 = 128 + k * 32;
            unsigned b00 = *(const unsigned*)(wrow + k0 +      tq * 4);
            unsigned b01 = *(const unsigned*)(wrow + k0 + 16 + tq * 4);
            unsigned b10 = *(const unsigned*)(wrow + k1 +      tq * 4);
            unsigned b11 = *(const unsigned*)(wrow + k1 + 16 + tq * 4);
            mma_u8s8(c0, a[k],     b00, b01);    // independent chains
            mma_u8s8(c1, a[4 + k], b10, b11);
        }
        int rr[4];
        #pragma unroll
        for (int e = 0; e < 4; e++) rr[e] = rne1792(c0[e]) + rne1792(c1[e]);

        // stage int8 codes: c0,c1 -> row g ; c2,c3 -> row g+8
        int col = n0 + nf * 8 + tq * 2;
        unsigned short p01 = (unsigned short)((rr[0] & 0xFF) | ((rr[1] & 0xFF) << 8));
        unsigned short p23 = (unsigned short)((rr[2] & 0xFF) | ((rr[3] & 0xFF) << 8));
        *(unsigned short*)(codes + (m0 + g    ) * 256 + col) = p01;
        *(unsigned short*)(codes + (m0 + g + 8) * 256 + col) = p23;
    }
    __syncthreads();

    // --- per-channel integer stats (exact, deterministic, overlapped atomics) ---
    int s = 0, s2 = 0;
    #pragma unroll
    for (int r = 0; r < BM; r++) {
        int v = (int)codes[r * 256 + tid];
        s += v; s2 += v * v;
    }
    atomicAdd(&g_csum [tid], s);
    atomicAdd(&g_csum2[tid], s2);

    // --- coalesced code writeout (contiguous 16KB block) ---
    int4* dst = (int4*)(g_codes + (size_t)blockIdx.x * BM * FOUT);
    const int4* src = (const int4*)codes;
    #pragma unroll
    for (int i = 0; i < 4; i++)
        dst[tid + i * 256] = src[tid + i * 256];
}

// ---------------- kernel D: build table (per block) + pure gather ----------------
__global__ void __launch_bounds__(256) kD(const float* __restrict__ gamma,
                                          const float* __restrict__ beta,
                                          float* __restrict__ out) {
    __shared__ float tab[FOUT * 33];              // 33792 B
    {
        int o = threadIdx.x;
        float sw15 = g_params[1];
        double C  = 1792.0 * (double)sw15;
        double s  = (double)g_csum[o];
        double s2 = (double)g_csum2[o];
        double mu = C * s / 65536.0;
        double m2 = C * C * s2 / 65536.0;
        double var = m2 - mu * mu;
        float t = (float)var + 1e-5f;
        float rs = (float)(1.0 / sqrt((double)t));
        float muf = (float)mu, gm = gamma[o], bt = beta[o];
        #pragma unroll
        for (int n = 0; n < 33; n++) {
            float acc = __fmul_rn((float)((n - 16) * 1792), sw15);
            float y = ((acc - muf) * rs) * gm + bt;
            float q = rintf(fminf(fmaxf(y, 0.0f), 1.0f) * 15.0f);
            tab[o * 33 + n] = __fdiv_rn(q, 15.0f);
        }
    }
    __syncthreads();

    size_t base = (size_t)blockIdx.x * 8192 + threadIdx.x;   // char4 indices
    #pragma unroll 4
    for (int i = 0; i < 32; i++) {
        size_t i4 = base + (size_t)i * 256;
        char4 cc = ((const char4*)g_codes)[i4];
        int o = ((int)(i4 & 63)) * 4;
        float4 r;
        r.x = tab[(o + 0) * 33 + (int)cc.x + 16];
        r.y = tab[(o + 1) * 33 + (int)cc.y + 16];
        r.z = tab[(o + 2) * 33 + (int)cc.z + 16];
        r.w = tab[(o + 3) * 33 + (int)cc.w + 16];
        ((float4*)out)[i4] = r;
    }
}

// ---------------- host launch ----------------
extern "C" void kernel_launch(void* const* d_in, const int* in_sizes, int n_in,
                              void* d_out, int out_size) {
    const float* x     = (const float*)d_in[0];
    const float* w     = (const float*)d_in[1];
    const float* gamma = (const float*)d_in[2];
    const float* beta  = (const float*)d_in[3];
    float* out = (float*)d_out;

    cudaFuncSetAttribute(kB, cudaFuncAttributeMaxDynamicSharedMemorySize, SMEM_B);

    kA1<<<64, 256>>>(w);
    kA2<<<64, 256>>>(w);
    kB <<<BATCH / BM, 256, SMEM_B>>>(x);
    kD <<<512, 256>>>(gamma, beta, out);          // 512 * 8192 char4 = 4194304
    (void)in_sizes; (void)n_in; (void)out_size;
}

// round 8
// speedup vs baseline: 1.0788x; 1.0453x over previous
#include <cuda_runtime.h>
#include <cstdint>

#define FIN   256
#define FOUT  256
#define BATCH 65536
#define BM    64          // batch rows per CTA in GEMM pass
#define WSTRIDE 272       // padded smem row stride (bytes) -> conflict-free frag loads
#define SMEM_B (FOUT*WSTRIDE + BM*WSTRIDE)   // 87040 bytes

// ---------------- device scratch ----------------
__device__ unsigned int g_bmax[64];             // per-block |w| max bits
__device__ float        g_params[2];            // [0]=scale_w, [1]=scale_w/15
__device__ int          g_csum [FOUT];
__device__ int          g_csum2[FOUT];
__device__ __align__(16) signed char g_wq[FOUT*FIN];   // quantized weights s8
__device__ signed char  g_codes[(size_t)BATCH*FOUT];   // 16MB int8 acc codes

// ---------------- helpers ----------------
__device__ __forceinline__ void mma_u8s8(int* c, const unsigned* a, unsigned b0, unsigned b1) {
    asm volatile(
        "mma.sync.aligned.m16n8k32.row.col.s32.u8.s8.s32 "
        "{%0,%1,%2,%3},{%4,%5,%6,%7},{%8,%9},{%0,%1,%2,%3};"
        : "+r"(c[0]), "+r"(c[1]), "+r"(c[2]), "+r"(c[3])
        : "r"(a[0]), "r"(a[1]), "r"(a[2]), "r"(a[3]), "r"(b0), "r"(b1));
}
__device__ __forceinline__ unsigned qact(float v) {
    return (unsigned)(int)rintf(fminf(fmaxf(v, 0.0f), 1.0f) * 15.0f);
}
// exact round-half-even(p/1792), p integer in [-13440, 13440]
__device__ __forceinline__ int rne1792(int p) {
    unsigned pp = (unsigned)(p + 15232);          // p + 896 + 8*1792 >= 0
    unsigned q = pp / 1792u;                      // umulhi + shift
    unsigned rem = pp - q * 1792u;
    int r = (int)q - 8;
    if (rem == 0u) r -= (r & 1);                  // tie -> even
    return r;
}

// ---------------- kernel A1: per-block max|W| (+ stat zeroing by block 0) ----------------
__global__ void kA1(const float* __restrict__ w) {
    if (blockIdx.x == 0) {                        // zero accumulators before kB
        g_csum [threadIdx.x] = 0;
        g_csum2[threadIdx.x] = 0;
    }
    int j = blockIdx.x * 256 + threadIdx.x;       // float4 id, 16384 total
    float4 v = ((const float4*)w)[j];
    unsigned m = max(max(__float_as_uint(fabsf(v.x)), __float_as_uint(fabsf(v.y))),
                     max(__float_as_uint(fabsf(v.z)), __float_as_uint(fabsf(v.w))));
    #pragma unroll
    for (int o = 16; o; o >>= 1) m = max(m, __shfl_xor_sync(0xffffffffu, m, o));
    __shared__ unsigned sm[8];
    if ((threadIdx.x & 31) == 0) sm[threadIdx.x >> 5] = m;
    __syncthreads();
    if (threadIdx.x == 0) {
        #pragma unroll
        for (int i = 1; i < 8; i++) m = max(m, sm[i]);
        g_bmax[blockIdx.x] = m;
    }
}

// ---------------- kernel A2: reduce max, quantize weights ----------------
__global__ void kA2(const float* __restrict__ w) {
    __shared__ unsigned sm[64];
    __shared__ float sscale;
    int tid = threadIdx.x;
    if (tid < 64) sm[tid] = g_bmax[tid];
    __syncthreads();
    if (tid == 0) {
        unsigned m = sm[0];
        #pragma unroll
        for (int i = 1; i < 64; i++) m = max(m, sm[i]);
        float scale = __fdiv_rn(__uint_as_float(m), 7.0f);
        sscale = scale;
        if (blockIdx.x == 0) {
            g_params[0] = scale;
            g_params[1] = __fdiv_rn(scale, 15.0f);
        }
    }
    __syncthreads();
    float scale = sscale;
    int j = blockIdx.x * 256 + tid;               // float4 id
    float4 v = ((const float4*)w)[j];
    char4 q;
    q.x = (signed char)(int)rintf(fminf(fmaxf(__fdiv_rn(v.x, scale), -7.0f), 7.0f));
    q.y = (signed char)(int)rintf(fminf(fmaxf(__fdiv_rn(v.y, scale), -7.0f), 7.0f));
    q.z = (signed char)(int)rintf(fminf(fmaxf(__fdiv_rn(v.z, scale), -7.0f), 7.0f));
    q.w = (signed char)(int)rintf(fminf(fmaxf(__fdiv_rn(v.w, scale), -7.0f), 7.0f));
    ((char4*)g_wq)[j] = q;
}

// ---------------- kernel B: quantize x + int8 GEMM + psum-quant + stats ----------------
__global__ void __launch_bounds__(256, 2) kB(const float* __restrict__ x) {
    extern __shared__ unsigned char sm[];
    unsigned char* w_s = sm;                  // [FOUT][WSTRIDE]
    unsigned char* x_s = sm + FOUT * WSTRIDE; // [BM][WSTRIDE], later reused as codes
    signed char*   codes = (signed char*)x_s; // [BM][256]

    const int tid = threadIdx.x;

    // --- load quantized weights (64KB, L2-hot) ---
    const int4* wg = (const int4*)g_wq;
    #pragma unroll
    for (int i = 0; i < 16; i++) {
        int j = tid + i * 256;          // int4 idx 0..4095
        int row = j >> 4, col = j & 15;
        *(int4*)(w_s + row * WSTRIDE + col * 16) = wg[j];
    }
    // --- load + quantize activations ---
    const float4* xg = (const float4*)(x + (size_t)blockIdx.x * BM * FIN);
    #pragma unroll
    for (int i = 0; i < 16; i++) {
        int j = tid + i * 256;          // float4 idx 0..4095
        float4 v = xg[j];
        int row = j >> 6, c4 = j & 63;
        unsigned p = qact(v.x) | (qact(v.y) << 8) | (qact(v.z) << 16) | (qact(v.w) << 24);
        *(unsigned*)(x_s + row * WSTRIDE + c4 * 4) = p;
    }
    __syncthreads();

    const int warp = tid >> 5, lane = tid & 31;
    const int g = lane >> 2, tq = lane & 3;
    const int m0 = (warp & 3) * 16;     // m16 fragment base row
    const int n0 = (warp >> 2) * 128;   // 128 output channels per warp-half

    // --- preload all A fragments for this warp (2 tiles x 4 ksteps) ---
    unsigned a[8][4];
    #pragma unroll
    for (int tk = 0; tk < 8; tk++) {
        int koff = tk * 32;
        a[tk][0] = *(const unsigned*)(x_s + (m0 + g    ) * WSTRIDE + koff +      tq * 4);
        a[tk][1] = *(const unsigned*)(x_s + (m0 + g + 8) * WSTRIDE + koff +      tq * 4);
        a[tk][2] = *(const unsigned*)(x_s + (m0 + g    ) * WSTRIDE + koff + 16 + tq * 4);
        a[tk][3] = *(const unsigned*)(x_s + (m0 + g + 8) * WSTRIDE + koff + 16 + tq * 4);
    }
    __syncthreads();   // x_s region now free -> code staging

    // --- main MMA loop: 16 n-fragments; two crossbar-tile chains interleaved ---
    #pragma unroll 2
    for (int nf = 0; nf < 16; nf++) {
        const int nrow = n0 + nf * 8 + g;        // output channel row in w_s
        const unsigned char* wrow = w_s + nrow * WSTRIDE;
        int c0[4] = {0, 0, 0, 0};                // crossbar tile 0 chain
        int c1[4] = {0, 0, 0, 0};                // crossbar tile 1 chain
        #pragma unroll
        for (int k = 0; k < 4; k++) {
            int k0 = k * 32, k1 = 128 + k * 32;
            unsigned b00 = *(const unsigned*)(wrow + k0 +      tq * 4);
            unsigned b01 = *(const unsigned*)(wrow + k0 + 16 + tq * 4);
            unsigned b10 = *(const unsigned*)(wrow + k1 +      tq * 4);
            unsigned b11 = *(const unsigned*)(wrow + k1 + 16 + tq * 4);
            mma_u8s8(c0, a[k],     b00, b01);    // independent chains
            mma_u8s8(c1, a[4 + k], b10, b11);
        }
        int rr[4];
        #pragma unroll
        for (int e = 0; e < 4; e++) rr[e] = rne1792(c0[e]) + rne1792(c1[e]);

        // stage int8 codes: c0,c1 -> row g ; c2,c3 -> row g+8
        int col = n0 + nf * 8 + tq * 2;
        unsigned short p01 = (unsigned short)((rr[0] & 0xFF) | ((rr[1] & 0xFF) << 8));
        unsigned short p23 = (unsigned short)((rr[2] & 0xFF) | ((rr[3] & 0xFF) << 8));
        *(unsigned short*)(codes + (m0 + g    ) * 256 + col) = p01;
        *(unsigned short*)(codes + (m0 + g + 8) * 256 + col) = p23;
    }
    __syncthreads();

    // --- per-channel integer stats (exact, deterministic, overlapped atomics) ---
    int s = 0, s2 = 0;
    #pragma unroll
    for (int r = 0; r < BM; r++) {
        int v = (int)codes[r * 256 + tid];
        s += v; s2 += v * v;
    }
    atomicAdd(&g_csum [tid], s);
    atomicAdd(&g_csum2[tid], s2);

    // --- coalesced code writeout (contiguous 16KB block) ---
    int4* dst = (int4*)(g_codes + (size_t)blockIdx.x * BM * FOUT);
    const int4* src = (const int4*)codes;
    #pragma unroll
    for (int i = 0; i < 4; i++)
        dst[tid + i * 256] = src[tid + i * 256];
}

// ---------------- kernel D: BN params in registers + arithmetic BN/ReLU ----------------
__global__ void __launch_bounds__(256) kD(const float* __restrict__ gamma,
                                          const float* __restrict__ beta,
                                          float* __restrict__ out) {
    __shared__ float4 bn[FOUT];                   // mu, rs, gamma, beta
    __shared__ float lut[16];                     // q -> __fdiv_rn(q, 15)
    const int t = threadIdx.x;
    {
        float sw15 = g_params[1];
        double C  = 1792.0 * (double)sw15;
        double s  = (double)g_csum[t];
        double s2 = (double)g_csum2[t];
        double mu = C * s / 65536.0;
        double m2 = C * C * s2 / 65536.0;
        double var = m2 - mu * mu;
        float tt = (float)var + 1e-5f;
        float rs = (float)(1.0 / sqrt((double)tt));
        bn[t] = make_float4((float)mu, rs, gamma[t], beta[t]);
    }
    if (t < 16) lut[t] = __fdiv_rn((float)t, 15.0f);
    __syncthreads();

    // channel group is CONSTANT per thread: o = (i4 & 63) * 4 depends only on tid
    const int o = (t & 63) * 4;
    const float4 b0 = bn[o + 0], b1 = bn[o + 1], b2 = bn[o + 2], b3 = bn[o + 3];
    const float sw15 = g_params[1];

    size_t base = (size_t)blockIdx.x * 8192 + t;  // char4 indices
    #pragma unroll 4
    for (int i = 0; i < 32; i++) {
        size_t i4 = base + (size_t)i * 256;
        char4 cc = ((const char4*)g_codes)[i4];
        float4 r;
        {
            float acc = __fmul_rn((float)((int)cc.x * 1792), sw15);
            float y = ((acc - b0.x) * b0.y) * b0.z + b0.w;
            r.x = lut[(int)rintf(fminf(fmaxf(y, 0.0f), 1.0f) * 15.0f)];
        }
        {
            float acc = __fmul_rn((float)((int)cc.y * 1792), sw15);
            float y = ((acc - b1.x) * b1.y) * b1.z + b1.w;
            r.y = lut[(int)rintf(fminf(fmaxf(y, 0.0f), 1.0f) * 15.0f)];
        }
        {
            float acc = __fmul_rn((float)((int)cc.z * 1792), sw15);
            float y = ((acc - b2.x) * b2.y) * b2.z + b2.w;
            r.z = lut[(int)rintf(fminf(fmaxf(y, 0.0f), 1.0f) * 15.0f)];
        }
        {
            float acc = __fmul_rn((float)((int)cc.w * 1792), sw15);
            float y = ((acc - b3.x) * b3.y) * b3.z + b3.w;
            r.w = lut[(int)rintf(fminf(fmaxf(y, 0.0f), 1.0f) * 15.0f)];
        }
        ((float4*)out)[i4] = r;
    }
}

// ---------------- host launch ----------------
extern "C" void kernel_launch(void* const* d_in, const int* in_sizes, int n_in,
                              void* d_out, int out_size) {
    const float* x     = (const float*)d_in[0];
    const float* w     = (const float*)d_in[1];
    const float* gamma = (const float*)d_in[2];
    const float* beta  = (const float*)d_in[3];
    float* out = (float*)d_out;

    cudaFuncSetAttribute(kB, cudaFuncAttributeMaxDynamicSharedMemorySize, SMEM_B);

    kA1<<<64, 256>>>(w);
    kA2<<<64, 256>>>(w);
    kB <<<BATCH / BM, 256, SMEM_B>>>(x);
    kD <<<512, 256>>>(gamma, beta, out);          // 512 * 8192 char4 = 4194304
    (void)in_sizes; (void)n_in; (void)out_size;
}